// round 5
// baseline (speedup 1.0000x reference)
#include <cuda_runtime.h>
#include <math.h>

#define NB 262144
#define NP 8
#define NTHREADS 256
#define NBLOCKS (NB / NTHREADS)

__device__ double g_part[NBLOCKS];
__device__ unsigned int g_ticket;

__global__ void __launch_bounds__(NTHREADS)
ciou_kernel(const float* __restrict__ A, const float* __restrict__ Bm,
            float* __restrict__ out) {
    int b = blockIdx.x * blockDim.x + threadIdx.x;

    double val;
    {
        // ---- load both octagons (16 floats each, 4x float4) ----
        float axv[NP], ayv[NP], bxv[NP], byv[NP];
        const float4* pa4 = (const float4*)(A  + (size_t)b * 16);
        const float4* pb4 = (const float4*)(Bm + (size_t)b * 16);
        #pragma unroll
        for (int i = 0; i < 4; i++) {
            float4 fa = pa4[i], fb = pb4[i];
            axv[2*i]   = fa.x; ayv[2*i]   = fa.y;
            axv[2*i+1] = fa.z; ayv[2*i+1] = fa.w;
            bxv[2*i]   = fb.x; byv[2*i]   = fb.y;
            bxv[2*i+1] = fb.z; byv[2*i+1] = fb.w;
        }

        // ---- shoelace areas (vertices are CCW by construction) ----
        float area_a = 0.f, area_b = 0.f;
        #pragma unroll
        for (int i = 0; i < NP; i++) {
            int j = (i + 1) & 7;
            area_a += axv[i]*ayv[j] - ayv[i]*axv[j];
            area_b += bxv[i]*byv[j] - byv[i]*bxv[j];
        }
        area_a *= 0.5f; area_b *= 0.5f;

        // ---- edge vectors (register arrays; every access const-indexed) ----
        float eax[NP], eay[NP], ebx[NP], eby[NP];
        #pragma unroll
        for (int j = 0; j < NP; j++) {
            int k = (j + 1) & 7;
            eax[j] = axv[k] - axv[j]; eay[j] = ayv[k] - ayv[j];
            ebx[j] = bxv[k] - bxv[j]; eby[j] = byv[k] - byv[j];
        }

        // ---- candidate points for intersection polygon (reference order) ----
        float cx[80], cy[80];
        int   cnt = 0;
        float sx = 0.f, sy = 0.f;

        // vertices of A inside B
        #pragma unroll
        for (int i = 0; i < NP; i++) {
            bool in = true;
            #pragma unroll
            for (int j = 0; j < NP; j++) {
                float cr = ebx[j]*(ayv[i]-byv[j]) - eby[j]*(axv[i]-bxv[j]);
                in = in && (cr >= -1e-6f);
            }
            if (in) { cx[cnt]=axv[i]; cy[cnt]=ayv[i]; sx+=axv[i]; sy+=ayv[i]; cnt++; }
        }
        // vertices of B inside A
        #pragma unroll
        for (int i = 0; i < NP; i++) {
            bool in = true;
            #pragma unroll
            for (int j = 0; j < NP; j++) {
                float cr = eax[j]*(byv[i]-ayv[j]) - eay[j]*(bxv[i]-axv[j]);
                in = in && (cr >= -1e-6f);
            }
            if (in) { cx[cnt]=bxv[i]; cy[cnt]=byv[i]; sx+=bxv[i]; sy+=byv[i]; cnt++; }
        }
        // edge-edge intersections: divide-free acceptance test, IEEE divide
        // only for accepted points (bit-matches reference's t = tn/denom).
        #pragma unroll
        for (int i = 0; i < NP; i++) {
            float p1x = axv[i], p1y = ayv[i];
            float d1x = eax[i], d1y = eay[i];
            #pragma unroll
            for (int j = 0; j < NP; j++) {
                float d2x = ebx[j], d2y = eby[j];
                float denom = d1x*d2y - d1y*d2x;
                if (fabsf(denom) >= 1e-9f) {
                    float rx = bxv[j] - p1x, ry = byv[j] - p1y;
                    float tn = rx*d2y - ry*d2x;
                    float un = rx*d1y - ry*d1x;
                    float dd = denom, tn2 = tn, un2 = un;
                    if (dd < 0.f) { dd = -dd; tn2 = -tn2; un2 = -un2; }
                    if (tn2 >= 0.f && tn2 <= dd && un2 >= 0.f && un2 <= dd) {
                        float t  = tn / denom;            // IEEE, matches ref
                        float ix = p1x + t*d1x, iy = p1y + t*d1y;
                        cx[cnt]=ix; cy[cnt]=iy; sx+=ix; sy+=iy; cnt++;
                    }
                }
            }
        }

        // ---- intersection area: pseudo-angle sort around centroid + shoelace
        // pseudo-angle is strictly monotone in atan2 over (-pi, pi] ->
        // identical ordering -> identical polygon -> identical area.
        float inter = 0.f;
        if (cnt >= 3) {
            float inv = 1.f / (float)cnt;
            float ctx = sx * inv, cty = sy * inv;
            float ang[80];
            #pragma unroll 1
            for (int i = 0; i < cnt; i++) {
                float dx = cx[i] - ctx, dy = cy[i] - cty;
                float s  = fabsf(dx) + fabsf(dy);
                float r  = (s > 0.f) ? __fdividef(dx, s) : 1.f;
                ang[i] = (dy >= 0.f) ? (1.f - r) : (r - 1.f);
            }
            // stable insertion sort (matches jnp.argsort stability)
            #pragma unroll 1
            for (int i = 1; i < cnt; i++) {
                float a0 = ang[i], x0 = cx[i], y0 = cy[i];
                int j = i - 1;
                while (j >= 0 && ang[j] > a0) {
                    ang[j+1]=ang[j]; cx[j+1]=cx[j]; cy[j+1]=cy[j]; j--;
                }
                ang[j+1]=a0; cx[j+1]=x0; cy[j+1]=y0;
            }
            float s = 0.f;
            float px0 = cx[0], py0 = cy[0];
            float pxp = px0, pyp = py0;
            #pragma unroll 1
            for (int i = 1; i < cnt; i++) {
                float cxp = cx[i], cyp = cy[i];
                s += pxp*cyp - pyp*cxp;
                pxp = cxp; pyp = cyp;
            }
            s += pxp*py0 - pyp*px0;
            inter = fmaxf(0.5f * s, 0.f);
        }

        // ---- convex hull area of all 16 points (registerized Jarvis march) --
        float px_[16], py_[16];
        #pragma unroll
        for (int i = 0; i < NP; i++) {
            px_[i]      = axv[i]; py_[i]      = ayv[i];
            px_[i + NP] = bxv[i]; py_[i + NP] = byv[i];
        }
        int   si  = 0;
        float spx = px_[0], spy = py_[0];
        #pragma unroll
        for (int i = 1; i < 16; i++) {
            bool better = (py_[i] < spy) || (py_[i] == spy && px_[i] < spx);
            if (better) { si = i; spx = px_[i]; spy = py_[i]; }
        }

        float acc = 0.f;
        float cpx = spx, cpy = spy;
        #pragma unroll 1
        for (int step = 0; step < 16; step++) {
            int   nxt = -1;
            float vnx = 0.f, vny = 0.f, nd2 = 0.f;
            float nxx = 0.f, nxy = 0.f;
            #pragma unroll
            for (int p = 0; p < 16; p++) {
                float vx = px_[p] - cpx, vy = py_[p] - cpy;
                float d2 = vx*vx + vy*vy;
                if (d2 >= 1e-16f) {
                    bool take;
                    if (nxt < 0) take = true;
                    else {
                        float cr = vnx*vy - vny*vx;
                        take = (cr < 0.f) || (cr == 0.f && d2 > nd2);
                    }
                    if (take) {
                        nxt = p; vnx = vx; vny = vy; nd2 = d2;
                        nxx = px_[p]; nxy = py_[p];   // exact coords, no drift
                    }
                }
            }
            if (nxt < 0) break;
            acc += cpx*nxy - cpy*nxx;
            if (nxt == si) break;
            cpx = nxx; cpy = nxy;
        }
        float ch = 0.5f * acc;

        // ---- CIoU ----
        float uni  = area_a + area_b - inter;
        float iou  = inter / uni;
        float ciou = iou - (ch - uni) / ch;
        val = (double)ciou;
    }

    // ---- deterministic block reduction ----
    #pragma unroll
    for (int o = 16; o > 0; o >>= 1)
        val += __shfl_down_sync(0xffffffffu, val, o);
    __shared__ double ws[NTHREADS / 32];
    __shared__ bool is_last;
    int lane = threadIdx.x & 31;
    int w    = threadIdx.x >> 5;
    if (lane == 0) ws[w] = val;
    __syncthreads();
    if (w == 0) {
        val = (lane < (NTHREADS / 32)) ? ws[lane] : 0.0;
        #pragma unroll
        for (int o = 4; o > 0; o >>= 1)
            val += __shfl_down_sync(0xffffffffu, val, o);
        if (lane == 0) g_part[blockIdx.x] = val;
    }

    // ---- last block folds the partials (deterministic fixed-order sum) ----
    __threadfence();
    if (threadIdx.x == 0) {
        unsigned int t = atomicAdd(&g_ticket, 1u);
        is_last = (t == NBLOCKS - 1);
    }
    __syncthreads();
    if (is_last) {
        __threadfence();
        double v = 0.0;
        for (int i = threadIdx.x; i < NBLOCKS; i += NTHREADS) v += g_part[i];
        #pragma unroll
        for (int o = 16; o > 0; o >>= 1)
            v += __shfl_down_sync(0xffffffffu, v, o);
        if (lane == 0) ws[w] = v;
        __syncthreads();
        if (w == 0) {
            v = (lane < (NTHREADS / 32)) ? ws[lane] : 0.0;
            #pragma unroll
            for (int o = 4; o > 0; o >>= 1)
                v += __shfl_down_sync(0xffffffffu, v, o);
            if (lane == 0) {
                out[0] = (float)(v / (double)NB);
                g_ticket = 0;   // reset for next graph replay
            }
        }
    }
}

extern "C" void kernel_launch(void* const* d_in, const int* in_sizes, int n_in,
                              void* d_out, int out_size) {
    const float* a = (const float*)d_in[0];
    const float* b = (const float*)d_in[1];
    ciou_kernel<<<NBLOCKS, NTHREADS>>>(a, b, (float*)d_out);
}

// round 6
// speedup vs baseline: 1.5097x; 1.5097x over previous
#include <cuda_runtime.h>
#include <math.h>

#define NB 262144
#define NP 8
#define NTHREADS 256
#define NBLOCKS (NB / NTHREADS)
#define MAXC 40

__device__ double g_part[NBLOCKS];
__device__ unsigned int g_ticket;

__global__ void __launch_bounds__(NTHREADS, 2)
ciou_kernel(const float* __restrict__ A, const float* __restrict__ Bm,
            float* __restrict__ out) {
    int b = blockIdx.x * blockDim.x + threadIdx.x;

    double val;
    {
        // ---- load both octagons (16 floats each, 4x float4) ----
        float axv[NP], ayv[NP], bxv[NP], byv[NP];
        const float4* pa4 = (const float4*)(A  + (size_t)b * 16);
        const float4* pb4 = (const float4*)(Bm + (size_t)b * 16);
        #pragma unroll
        for (int i = 0; i < 4; i++) {
            float4 fa = pa4[i], fb = pb4[i];
            axv[2*i]   = fa.x; ayv[2*i]   = fa.y;
            axv[2*i+1] = fa.z; ayv[2*i+1] = fa.w;
            bxv[2*i]   = fb.x; byv[2*i]   = fb.y;
            bxv[2*i+1] = fb.z; byv[2*i+1] = fb.w;
        }

        // ---- shoelace areas (vertices are CCW by construction) ----
        float area_a = 0.f, area_b = 0.f;
        #pragma unroll
        for (int i = 0; i < NP; i++) {
            int j = (i + 1) & 7;
            area_a += axv[i]*ayv[j] - ayv[i]*axv[j];
            area_b += bxv[i]*byv[j] - byv[i]*bxv[j];
        }
        area_a *= 0.5f; area_b *= 0.5f;

        // ---- edge vectors ----
        float eax[NP], eay[NP], ebx[NP], eby[NP];
        #pragma unroll
        for (int j = 0; j < NP; j++) {
            int k = (j + 1) & 7;
            eax[j] = axv[k] - axv[j]; eay[j] = ayv[k] - ayv[j];
            ebx[j] = bxv[k] - bxv[j]; eby[j] = byv[k] - byv[j];
        }

        // ---- candidate points for intersection polygon (reference order) ----
        float cx[MAXC], cy[MAXC];
        int   cnt = 0;
        float sx = 0.f, sy = 0.f;

        // vertices of A inside B
        #pragma unroll
        for (int i = 0; i < NP; i++) {
            bool in = true;
            #pragma unroll
            for (int j = 0; j < NP; j++) {
                float cr = ebx[j]*(ayv[i]-byv[j]) - eby[j]*(axv[i]-bxv[j]);
                in = in && (cr >= -1e-6f);
            }
            if (in) { cx[cnt]=axv[i]; cy[cnt]=ayv[i]; sx+=axv[i]; sy+=ayv[i]; cnt++; }
        }
        // vertices of B inside A
        #pragma unroll
        for (int i = 0; i < NP; i++) {
            bool in = true;
            #pragma unroll
            for (int j = 0; j < NP; j++) {
                float cr = eax[j]*(byv[i]-ayv[j]) - eay[j]*(bxv[i]-axv[j]);
                in = in && (cr >= -1e-6f);
            }
            if (in) { cx[cnt]=bxv[i]; cy[cnt]=byv[i]; sx+=bxv[i]; sy+=byv[i]; cnt++; }
        }
        // edge-edge intersections: divide-free acceptance, IEEE divide only
        // on accepted points (bit-matches reference t = tn/denom).
        #pragma unroll 2
        for (int i = 0; i < NP; i++) {
            float p1x = axv[i], p1y = ayv[i];
            float d1x = eax[i], d1y = eay[i];
            #pragma unroll
            for (int j = 0; j < NP; j++) {
                float d2x = ebx[j], d2y = eby[j];
                float denom = d1x*d2y - d1y*d2x;
                if (fabsf(denom) >= 1e-9f) {
                    float rx = bxv[j] - p1x, ry = byv[j] - p1y;
                    float tn = rx*d2y - ry*d2x;
                    float un = rx*d1y - ry*d1x;
                    float dd = denom, tn2 = tn, un2 = un;
                    if (dd < 0.f) { dd = -dd; tn2 = -tn2; un2 = -un2; }
                    if (tn2 >= 0.f && tn2 <= dd && un2 >= 0.f && un2 <= dd) {
                        float t  = tn / denom;            // IEEE, matches ref
                        float ix = p1x + t*d1x, iy = p1y + t*d1y;
                        if (cnt < MAXC) {
                            cx[cnt]=ix; cy[cnt]=iy; sx+=ix; sy+=iy; cnt++;
                        }
                    }
                }
            }
        }

        // ---- intersection area: pseudo-angle sort around centroid + shoelace
        // pseudo-angle strictly monotone in atan2 over (-pi,pi] -> same order.
        float inter = 0.f;
        if (cnt >= 3) {
            float inv = 1.f / (float)cnt;
            float ctx = sx * inv, cty = sy * inv;
            float ang[MAXC];
            #pragma unroll 1
            for (int i = 0; i < cnt; i++) {
                float dx = cx[i] - ctx, dy = cy[i] - cty;
                float s  = fabsf(dx) + fabsf(dy);
                float r  = (s > 0.f) ? __fdividef(dx, s) : 1.f;
                ang[i] = (dy >= 0.f) ? (1.f - r) : (r - 1.f);
            }
            // stable insertion sort (matches jnp.argsort stability)
            #pragma unroll 1
            for (int i = 1; i < cnt; i++) {
                float a0 = ang[i], x0 = cx[i], y0 = cy[i];
                int j = i - 1;
                while (j >= 0 && ang[j] > a0) {
                    ang[j+1]=ang[j]; cx[j+1]=cx[j]; cy[j+1]=cy[j]; j--;
                }
                ang[j+1]=a0; cx[j+1]=x0; cy[j+1]=y0;
            }
            float s = 0.f;
            float px0 = cx[0], py0 = cy[0];
            float pxp = px0, pyp = py0;
            #pragma unroll 1
            for (int i = 1; i < cnt; i++) {
                float cxp = cx[i], cyp = cy[i];
                s += pxp*cyp - pyp*cxp;
                pxp = cxp; pyp = cyp;
            }
            s += pxp*py0 - pyp*px0;
            inter = fmaxf(0.5f * s, 0.f);
        }

        // ---- convex hull area of all 16 points (registerized Jarvis march) --
        float px_[16], py_[16];
        #pragma unroll
        for (int i = 0; i < NP; i++) {
            px_[i]      = axv[i]; py_[i]      = ayv[i];
            px_[i + NP] = bxv[i]; py_[i + NP] = byv[i];
        }
        int   si  = 0;
        float spx = px_[0], spy = py_[0];
        #pragma unroll
        for (int i = 1; i < 16; i++) {
            bool better = (py_[i] < spy) || (py_[i] == spy && px_[i] < spx);
            if (better) { si = i; spx = px_[i]; spy = py_[i]; }
        }

        float acc = 0.f;
        float cpx = spx, cpy = spy;
        #pragma unroll 1
        for (int step = 0; step < 16; step++) {
            int   nxt = -1;
            float vnx = 0.f, vny = 0.f, nd2 = 0.f;
            float nxx = 0.f, nxy = 0.f;
            #pragma unroll
            for (int p = 0; p < 16; p++) {
                float vx = px_[p] - cpx, vy = py_[p] - cpy;
                float d2 = vx*vx + vy*vy;
                if (d2 >= 1e-16f) {
                    bool take;
                    if (nxt < 0) take = true;
                    else {
                        float cr = vnx*vy - vny*vx;
                        take = (cr < 0.f) || (cr == 0.f && d2 > nd2);
                    }
                    if (take) {
                        nxt = p; vnx = vx; vny = vy; nd2 = d2;
                        nxx = px_[p]; nxy = py_[p];   // exact coords, no drift
                    }
                }
            }
            if (nxt < 0) break;
            acc += cpx*nxy - cpy*nxx;
            if (nxt == si) break;
            cpx = nxx; cpy = nxy;
        }
        float ch = 0.5f * acc;

        // ---- CIoU ----
        float uni  = area_a + area_b - inter;
        float iou  = inter / uni;
        float ciou = iou - (ch - uni) / ch;
        val = (double)ciou;
    }

    // ---- deterministic block reduction ----
    #pragma unroll
    for (int o = 16; o > 0; o >>= 1)
        val += __shfl_down_sync(0xffffffffu, val, o);
    __shared__ double ws[NTHREADS / 32];
    __shared__ bool is_last;
    int lane = threadIdx.x & 31;
    int w    = threadIdx.x >> 5;
    if (lane == 0) ws[w] = val;
    __syncthreads();
    if (w == 0) {
        val = (lane < (NTHREADS / 32)) ? ws[lane] : 0.0;
        #pragma unroll
        for (int o = 4; o > 0; o >>= 1)
            val += __shfl_down_sync(0xffffffffu, val, o);
        if (lane == 0) g_part[blockIdx.x] = val;
    }

    // ---- last block folds the partials (deterministic fixed-order sum) ----
    __threadfence();
    if (threadIdx.x == 0) {
        unsigned int t = atomicAdd(&g_ticket, 1u);
        is_last = (t == NBLOCKS - 1);
    }
    __syncthreads();
    if (is_last) {
        __threadfence();
        double v = 0.0;
        for (int i = threadIdx.x; i < NBLOCKS; i += NTHREADS) v += g_part[i];
        #pragma unroll
        for (int o = 16; o > 0; o >>= 1)
            v += __shfl_down_sync(0xffffffffu, v, o);
        if (lane == 0) ws[w] = v;
        __syncthreads();
        if (w == 0) {
            v = (lane < (NTHREADS / 32)) ? ws[lane] : 0.0;
            #pragma unroll
            for (int o = 4; o > 0; o >>= 1)
                v += __shfl_down_sync(0xffffffffu, v, o);
            if (lane == 0) {
                out[0] = (float)(v / (double)NB);
                g_ticket = 0;   // reset for next graph replay
            }
        }
    }
}

extern "C" void kernel_launch(void* const* d_in, const int* in_sizes, int n_in,
                              void* d_out, int out_size) {
    const float* a = (const float*)d_in[0];
    const float* b = (const float*)d_in[1];
    ciou_kernel<<<NBLOCKS, NTHREADS>>>(a, b, (float*)d_out);
}